// round 9
// baseline (speedup 1.0000x reference)
#include <cuda_runtime.h>
#include <cuda_fp16.h>
#include <math.h>
#include <stdint.h>

#define P 64
#define NMAX 4096

// ---------------- persistent device scratch ----------------
__device__ float g_sq[NMAX];
__device__ unsigned int g_maxbits;
__device__ float g_S1[NMAX];
__device__ float g_mun[NMAX * P];
__device__ float g_bU[NMAX];
__device__ float g_sU2[NMAX];
__device__ float g_S2[NMAX];
__device__ float g_accZ[NMAX * P];
__device__ __half g_xh[NMAX * P], g_xl[NMAX * P];
__device__ __half g_Uh[NMAX * P], g_Ul[NMAX * P];

// ---------------- helpers ----------------
__device__ __forceinline__ uint32_t su32(const void* p) {
    uint32_t a;
    asm("{ .reg .u64 t; cvta.to.shared.u64 t, %1; cvt.u32.u64 %0, t; }" : "=r"(a) : "l"(p));
    return a;
}
#define SWZ(b) ((uint32_t)(b) ^ ((((uint32_t)(b)) >> 3) & 0x70))

__device__ __forceinline__ uint32_t frag_addr(uint32_t base, int lane, int row0, int col0) {
    int r = row0 + (lane & 7) + ((lane >> 3) & 1) * 8;
    int cb = (col0 + (lane >> 4) * 8) * 2;
    return base + SWZ(r * 128 + cb);
}
__device__ __forceinline__ void ldm_x4(uint32_t* r, uint32_t a) {
    asm volatile("ldmatrix.sync.aligned.m8n8.x4.shared.b16 {%0,%1,%2,%3}, [%4];"
                 : "=r"(r[0]), "=r"(r[1]), "=r"(r[2]), "=r"(r[3]) : "r"(a));
}
__device__ __forceinline__ void ldm_x4t(uint32_t* r, uint32_t a) {
    asm volatile("ldmatrix.sync.aligned.m8n8.x4.trans.shared.b16 {%0,%1,%2,%3}, [%4];"
                 : "=r"(r[0]), "=r"(r[1]), "=r"(r[2]), "=r"(r[3]) : "r"(a));
}
__device__ __forceinline__ void mma16816(float* c, const uint32_t* a, const uint32_t* b) {
    asm volatile(
        "mma.sync.aligned.m16n8k16.row.col.f32.f16.f16.f32 "
        "{%0,%1,%2,%3}, {%4,%5,%6,%7}, {%8,%9}, {%0,%1,%2,%3};"
        : "+f"(c[0]), "+f"(c[1]), "+f"(c[2]), "+f"(c[3])
        : "r"(a[0]), "r"(a[1]), "r"(a[2]), "r"(a[3]), "r"(b[0]), "r"(b[1]));
}
__device__ __forceinline__ uint32_t packh2(float a, float b) {
    __half2 h = __floats2half2_rn(a, b);
    return *(uint32_t*)&h;
}
__device__ __forceinline__ void cp16(uint32_t d, const void* s) {
    asm volatile("cp.async.cg.shared.global [%0], [%1], 16;" :: "r"(d), "l"(s));
}
#define CP_COMMIT() asm volatile("cp.async.commit_group;" ::: "memory")
#define CP_WAIT(N)  asm volatile("cp.async.wait_group %0;" :: "n"(N) : "memory")

__device__ __forceinline__ float asqrt(float x) { float r; asm("sqrt.approx.f32 %0,%1;" : "=f"(r) : "f"(x)); return r; }
__device__ __forceinline__ float w1f(float d2, float R2i) {
    float s = fmaxf(fmaf(-d2, R2i, 1.0f), 0.0f);
    return s * s * s;
}
__device__ __forceinline__ float w2f(float d, float a) {
    float t = __saturatef(fmaf(d, a, -1.0f));
    float s = fmaf(-t, t, 1.0f);
    return s * s * s;
}

// ---------------- K: prep — sq norms + fp16 split + zero-init ----------------
__global__ void k_prep(const float* __restrict__ x, int n) {
    int gt = blockIdx.x * blockDim.x + threadIdx.x;
    int w = gt >> 5;
    int lane = threadIdx.x & 31;
    *(float2*)&g_mun[(size_t)gt * 2] = make_float2(0.f, 0.f);
    if (gt < n) g_S1[gt] = 0.f;
    if (gt == 0) g_maxbits = 0u;
    if (w >= n) return;
    float v0 = x[(size_t)w * P + lane], v1 = x[(size_t)w * P + 32 + lane];
    __half h0 = __float2half_rn(v0), h1 = __float2half_rn(v1);
    g_xh[(size_t)w * P + lane] = h0;
    g_xh[(size_t)w * P + 32 + lane] = h1;
    g_xl[(size_t)w * P + lane] = __float2half_rn(v0 - __half2float(h0));
    g_xl[(size_t)w * P + 32 + lane] = __float2half_rn(v1 - __half2float(h1));
    float s = v0 * v0 + v1 * v1;
    #pragma unroll
    for (int o = 16; o; o >>= 1) s += __shfl_xor_sync(0xffffffffu, s, o);
    if (lane == 0) g_sq[w] = s;
}

// ---------------- K: gram-max — max d2 over upper triangle (no stores) ----------------
// dyn smem: Ah 0 (16K), Bh 16384 (16K), Bl 32768 (16K), sqi 49152(512), sqj 49664(512)
__global__ void __launch_bounds__(256) k_grammax(int n) {
    extern __shared__ char smc[];
    __shared__ float wmax[8];
    uint32_t sb = su32(smc);
    const int t = threadIdx.x, w = t >> 5, lane = t & 31;
    const int nb = n >> 7;
    int k = blockIdx.x, a = 0;
    while (k >= nb - a) { k -= nb - a; a++; }
    const int i0 = a * 128, j0 = (a + k) * 128;
    float* sqi = (float*)(smc + 49152);
    float* sqj = (float*)(smc + 49664);

    for (int q = t; q < 1024; q += 256) {
        int row = q >> 3, cb = (q & 7) * 16;
        uint32_t off = SWZ(row * 128 + cb);
        *(uint4*)(smc + off)         = *(const uint4*)&g_xh[(size_t)(i0 + row) * P + cb / 2];
        *(uint4*)(smc + 16384 + off) = *(const uint4*)&g_xh[(size_t)(j0 + row) * P + cb / 2];
        *(uint4*)(smc + 32768 + off) = *(const uint4*)&g_xl[(size_t)(j0 + row) * P + cb / 2];
    }
    if (t < 128) sqi[t] = g_sq[i0 + t];
    else sqj[t - 128] = g_sq[j0 + t - 128];
    __syncthreads();

    const int m0 = (w & 3) * 32, n0w = (w >> 2) * 64;
    float C[2][8][4];
    #pragma unroll
    for (int a2 = 0; a2 < 2; a2++)
        #pragma unroll
        for (int b = 0; b < 8; b++)
            #pragma unroll
            for (int e = 0; e < 4; e++) C[a2][b][e] = 0.f;

    #pragma unroll
    for (int ks = 0; ks < 4; ks++) {
        int k0 = ks * 16;
        uint32_t Ah[2][4];
        #pragma unroll
        for (int mi = 0; mi < 2; mi++)
            ldm_x4(Ah[mi], frag_addr(sb, lane, m0 + mi * 16, k0));
        #pragma unroll
        for (int gq = 0; gq < 4; gq++) {
            uint32_t Bh[4], Bl[4];
            ldm_x4(Bh, frag_addr(sb + 16384, lane, n0w + gq * 16, k0));
            ldm_x4(Bl, frag_addr(sb + 32768, lane, n0w + gq * 16, k0));
            #pragma unroll
            for (int h = 0; h < 2; h++) {
                int ni = gq * 2 + h;
                uint32_t bh[2] = {Bh[h], Bh[h + 2]};
                uint32_t bl[2] = {Bl[h], Bl[h + 2]};
                #pragma unroll
                for (int mi = 0; mi < 2; mi++) {
                    mma16816(C[mi][ni], Ah[mi], bh);
                    mma16816(C[mi][ni], Ah[mi], bl);
                }
            }
        }
    }
    const int g = lane >> 2, tg = lane & 3;
    float lmax = 0.f;
    #pragma unroll
    for (int mi = 0; mi < 2; mi++)
        #pragma unroll
        for (int e2 = 0; e2 < 2; e2++) {
            int i = m0 + mi * 16 + g + e2 * 8;
            float si = sqi[i];
            #pragma unroll
            for (int ni = 0; ni < 8; ni++) {
                int j = n0w + ni * 8 + tg * 2;
                float d0 = si + sqj[j]     - 2.f * C[mi][ni][e2 * 2];
                float d1 = si + sqj[j + 1] - 2.f * C[mi][ni][e2 * 2 + 1];
                lmax = fmaxf(lmax, fmaxf(d0, d1));
            }
        }
    lmax = fmaxf(lmax, 0.f);
    #pragma unroll
    for (int o = 16; o; o >>= 1) lmax = fmaxf(lmax, __shfl_xor_sync(0xffffffffu, lmax, o));
    if (lane == 0) wmax[w] = lmax;
    __syncthreads();
    if (t == 0) {
        float m = wmax[0];
        #pragma unroll
        for (int q = 1; q < 8; q++) m = fmaxf(m, wmax[q]);
        atomicMax(&g_maxbits, __float_as_uint(m));
    }
}

// ---------------- K: alpha — in-kernel d2 (G-GEMM) + w1 + W@x ----------------
// dyn smem: Wh 0 (16K), xb0h 16384, xb0l 24576, xb1h 32768, xb1l 40960,
//           sqj 49152(512), sqi 49664(512) -> 50176 ; grid (n/128, 32), 2 chunks
__global__ void __launch_bounds__(256, 2) k_alpha(const float* __restrict__ pr0, int n) {
    extern __shared__ char smc[];
    uint32_t sb = su32(smc);
    const int t = threadIdx.x, w = t >> 5, lane = t & 31;
    const int g = lane >> 2, tg = lane & 3;
    const int j0 = blockIdx.x * 128;
    const int ib0 = blockIdx.y * 128;
    float* sqjs = (float*)(smc + 49152);
    float* sqis = (float*)(smc + 49664);
    const float r0v = fminf(*pr0, sqrtf(__uint_as_float(g_maxbits)));
    const float R2i = 1.0f / (r0v * r0v);

    // issue chunk0 x-tile cp.async (xh+xl of rows ib0..+63)
    #pragma unroll
    for (int m = 0; m < 4; m++) {
        int q = t + 256 * m;
        if (q < 512) {
            int row = q >> 3, cb = (q & 7) * 16;
            cp16(sb + 16384 + SWZ(row * 128 + cb), &g_xh[(size_t)(ib0 + row) * P + cb / 2]);
        } else {
            int q2 = q - 512;
            int row = q2 >> 3, cb = (q2 & 7) * 16;
            cp16(sb + 24576 + SWZ(row * 128 + cb), &g_xl[(size_t)(ib0 + row) * P + cb / 2]);
        }
    }
    CP_COMMIT();
    // stage xh_j into Wh area (for G A-fragments)
    for (int q = t; q < 1024; q += 256) {
        int row = q >> 3, cb = (q & 7) * 16;
        *(uint4*)(smc + SWZ(row * 128 + cb)) = *(const uint4*)&g_xh[(size_t)(j0 + row) * P + cb / 2];
    }
    if (t < 128) sqjs[t] = g_sq[j0 + t];
    else sqis[t - 128] = g_sq[ib0 + t - 128];
    __syncthreads();
    uint32_t AXh[4][4];
    #pragma unroll
    for (int ks = 0; ks < 4; ks++)
        ldm_x4(AXh[ks], frag_addr(sb, lane, w * 16, ks * 16));

    float C[8][4];
    #pragma unroll
    for (int b = 0; b < 8; b++)
        #pragma unroll
        for (int e = 0; e < 4; e++) C[b][e] = 0.f;
    float rs[2] = {0.f, 0.f};

    #pragma unroll
    for (int ch = 0; ch < 2; ch++) {
        if (ch) __syncthreads();
        if (ch == 0) {
            #pragma unroll
            for (int m = 0; m < 4; m++) {
                int q = t + 256 * m;
                if (q < 512) {
                    int row = q >> 3, cb = (q & 7) * 16;
                    cp16(sb + 32768 + SWZ(row * 128 + cb), &g_xh[(size_t)(ib0 + 64 + row) * P + cb / 2]);
                } else {
                    int q2 = q - 512;
                    int row = q2 >> 3, cb = (q2 & 7) * 16;
                    cp16(sb + 40960 + SWZ(row * 128 + cb), &g_xl[(size_t)(ib0 + 64 + row) * P + cb / 2]);
                }
            }
            CP_COMMIT();
            CP_WAIT(1);
        } else {
            CP_WAIT(0);
        }
        __syncthreads();
        uint32_t xbh = sb + 16384 + ch * 16384;
        uint32_t xbl = xbh + 8192;
        // G-GEMM: G[j][i] (2-term)
        float gC[8][4];
        #pragma unroll
        for (int b = 0; b < 8; b++)
            #pragma unroll
            for (int e = 0; e < 4; e++) gC[b][e] = 0.f;
        #pragma unroll
        for (int ks = 0; ks < 4; ks++) {
            int k0 = ks * 16;
            #pragma unroll
            for (int gq = 0; gq < 4; gq++) {
                uint32_t Bh[4], Bl[4];
                ldm_x4(Bh, frag_addr(xbh, lane, gq * 16, k0));
                ldm_x4(Bl, frag_addr(xbl, lane, gq * 16, k0));
                #pragma unroll
                for (int h = 0; h < 2; h++) {
                    int ni = gq * 2 + h;
                    uint32_t bh[2] = {Bh[h], Bh[h + 2]};
                    uint32_t bl[2] = {Bl[h], Bl[h + 2]};
                    mma16816(gC[ni], AXh[ks], bh);
                    mma16816(gC[ni], AXh[ks], bl);
                }
            }
        }
        // weights from fragments -> Wh
        #pragma unroll
        for (int e2 = 0; e2 < 2; e2++) {
            int jl = w * 16 + g + e2 * 8;
            float sj = sqjs[jl];
            #pragma unroll
            for (int ni = 0; ni < 8; ni++) {
                int il = ni * 8 + tg * 2;
                float d0 = sj + sqis[ch * 64 + il]     - 2.f * gC[ni][e2 * 2];
                float d1 = sj + sqis[ch * 64 + il + 1] - 2.f * gC[ni][e2 * 2 + 1];
                float w0 = w1f(d0, R2i), w1v = w1f(d1, R2i);
                rs[e2] += w0 + w1v;
                *(uint32_t*)(smc + SWZ(jl * 128 + il * 2)) = packh2(w0, w1v);
            }
        }
        __syncthreads();
        // W@x (1 term)
        #pragma unroll
        for (int ks = 0; ks < 4; ks++) {
            int k0 = ks * 16;
            uint32_t Awh[4];
            ldm_x4(Awh, frag_addr(sb, lane, w * 16, k0));
            #pragma unroll
            for (int gq = 0; gq < 4; gq++) {
                uint32_t Bh[4];
                ldm_x4t(Bh, frag_addr(xbh, lane, k0, gq * 16));
                #pragma unroll
                for (int h = 0; h < 2; h++) {
                    uint32_t bh[2] = {Bh[h * 2], Bh[h * 2 + 1]};
                    mma16816(C[gq * 2 + h], Awh, bh);
                }
            }
        }
    }
    // epilogue
    #pragma unroll
    for (int e2 = 0; e2 < 2; e2++) {
        float s = rs[e2];
        s += __shfl_xor_sync(0xffffffffu, s, 1);
        s += __shfl_xor_sync(0xffffffffu, s, 2);
        if (tg == 0) atomicAdd(&g_S1[j0 + w * 16 + g + e2 * 8], s);
    }
    #pragma unroll
    for (int ni = 0; ni < 8; ni++)
        #pragma unroll
        for (int e = 0; e < 4; e++) {
            int j = j0 + w * 16 + g + (e >> 1) * 8;
            int p = ni * 8 + tg * 2 + (e & 1);
            atomicAdd(&g_mun[(size_t)j * P + p], C[ni][e]);
        }
}

// ---------------- K: U = x - mu (+ splits), bU, sqrt(||U||^2), zero-init ----------------
__global__ void k_U(const float* __restrict__ x, int n) {
    int gt = blockIdx.x * blockDim.x + threadIdx.x;
    int w = gt >> 5;
    int lane = threadIdx.x & 31;
    *(float2*)&g_accZ[(size_t)gt * 2] = make_float2(0.f, 0.f);
    if (gt < n) g_S2[gt] = 0.f;
    if (w >= n) return;
    float S1 = g_S1[w];
    float b = 0.f, un2 = 0.f;
    #pragma unroll
    for (int h = 0; h < 2; h++) {
        int p = lane + 32 * h;
        float mu = g_mun[(size_t)w * P + p] / S1;
        float xv = x[(size_t)w * P + p];
        if (isnan(mu)) mu = xv;
        float U = xv - mu;
        __half uh = __float2half_rn(U);
        g_Uh[(size_t)w * P + p] = uh;
        g_Ul[(size_t)w * P + p] = __float2half_rn(U - __half2float(uh));
        b += xv * U;
        un2 += U * U;
    }
    #pragma unroll
    for (int o = 16; o; o >>= 1) {
        b += __shfl_xor_sync(0xffffffffu, b, o);
        un2 += __shfl_xor_sync(0xffffffffu, un2, o);
    }
    if (lane == 0) { g_bU[w] = b; g_sU2[w] = sqrtf(un2); }
}

// ---------------- K: beta — in-kernel d2 + c-GEMM(x3) + weights + acc-GEMM(x1) ----------------
// dyn smem: Wh 0 (16K), Dst 16384 (16K), Xj 32768 (16K),
//           xb0h 49152, xb0l 57344, xb1h 65536, xb1l 73728 (8K each),
//           sqj 81920(512), sqi 82432(1K), bU 83456(512), su2 83968(512) -> 84480
// grid (n/128, 16), 4 chunks
__global__ void __launch_bounds__(256, 2) k_beta(const float* __restrict__ pr1,
                                                 const float* __restrict__ pr2, int n) {
    extern __shared__ char smc[];
    uint32_t sb = su32(smc);
    float* sqjs = (float*)(smc + 81920);
    float* sqis = (float*)(smc + 82432);
    float* bUs  = (float*)(smc + 83456);
    float* su2s = (float*)(smc + 83968);
    const int t = threadIdx.x, w = t >> 5, lane = t & 31;
    const int g = lane >> 2, tg = lane & 3;
    const int j0 = blockIdx.x * 128;
    const int ib0 = blockIdx.y * 256;
    const float md = sqrtf(__uint_as_float(g_maxbits));
    const float rr1 = fminf(*pr1, md), rr2 = fminf(*pr2, md);
    const float a1 = 2.0f / rr1, a2 = 2.0f / rr2;

    // issue chunk0 x tiles
    #pragma unroll
    for (int m = 0; m < 4; m++) {
        int q = t + 256 * m;
        if (q < 512) {
            int row = q >> 3, cb = (q & 7) * 16;
            cp16(sb + 49152 + SWZ(row * 128 + cb), &g_xh[(size_t)(ib0 + row) * P + cb / 2]);
        } else {
            int q2 = q - 512;
            int row = q2 >> 3, cb = (q2 & 7) * 16;
            cp16(sb + 57344 + SWZ(row * 128 + cb), &g_xl[(size_t)(ib0 + row) * P + cb / 2]);
        }
    }
    CP_COMMIT();
    // stage Uh -> Wh, Ul -> Dst, xh_j -> Xj
    for (int q = t; q < 1024; q += 256) {
        int row = q >> 3, cb = (q & 7) * 16;
        uint32_t off = SWZ(row * 128 + cb);
        *(uint4*)(smc + off)         = *(const uint4*)&g_Uh[(size_t)(j0 + row) * P + cb / 2];
        *(uint4*)(smc + 16384 + off) = *(const uint4*)&g_Ul[(size_t)(j0 + row) * P + cb / 2];
        *(uint4*)(smc + 32768 + off) = *(const uint4*)&g_xh[(size_t)(j0 + row) * P + cb / 2];
    }
    if (t < 128) {
        bUs[t] = g_bU[j0 + t];
        su2s[t] = g_sU2[j0 + t];
        sqjs[t] = g_sq[j0 + t];
    } else {
        int t2 = t - 128;
        sqis[t2]       = g_sq[ib0 + t2];
        sqis[t2 + 128] = g_sq[ib0 + 128 + t2];
    }
    __syncthreads();
    uint32_t AUh[4][4], AUl[4][4], AXh[4][4];
    #pragma unroll
    for (int ks = 0; ks < 4; ks++) {
        ldm_x4(AUh[ks], frag_addr(sb,         lane, w * 16, ks * 16));
        ldm_x4(AUl[ks], frag_addr(sb + 16384, lane, w * 16, ks * 16));
        ldm_x4(AXh[ks], frag_addr(sb + 32768, lane, w * 16, ks * 16));
    }

    float accC[8][4];
    #pragma unroll
    for (int b = 0; b < 8; b++)
        #pragma unroll
        for (int e = 0; e < 4; e++) accC[b][e] = 0.f;
    float rs2[2] = {0.f, 0.f};

    #pragma unroll 1
    for (int ch = 0; ch < 4; ch++) {
        if (ch) __syncthreads();
        if (ch < 3) {
            uint32_t bh_dst = sb + 49152 + ((ch + 1) & 1) * 16384;
            int ibn = ib0 + (ch + 1) * 64;
            #pragma unroll
            for (int m = 0; m < 4; m++) {
                int q = t + 256 * m;
                if (q < 512) {
                    int row = q >> 3, cb = (q & 7) * 16;
                    cp16(bh_dst + SWZ(row * 128 + cb), &g_xh[(size_t)(ibn + row) * P + cb / 2]);
                } else {
                    int q2 = q - 512;
                    int row = q2 >> 3, cb = (q2 & 7) * 16;
                    cp16(bh_dst + 8192 + SWZ(row * 128 + cb), &g_xl[(size_t)(ibn + row) * P + cb / 2]);
                }
            }
            CP_COMMIT();
            CP_WAIT(1);
        } else {
            CP_WAIT(0);
        }
        __syncthreads();
        uint32_t xbh = sb + 49152 + (ch & 1) * 16384;
        uint32_t xbl = xbh + 8192;

        // G-GEMM (2-term) -> d2 packed into Dst
        {
            float gC[8][4];
            #pragma unroll
            for (int b = 0; b < 8; b++)
                #pragma unroll
                for (int e = 0; e < 4; e++) gC[b][e] = 0.f;
            #pragma unroll
            for (int ks = 0; ks < 4; ks++) {
                int k0 = ks * 16;
                #pragma unroll
                for (int gq = 0; gq < 4; gq++) {
                    uint32_t Bh[4], Bl[4];
                    ldm_x4(Bh, frag_addr(xbh, lane, gq * 16, k0));
                    ldm_x4(Bl, frag_addr(xbl, lane, gq * 16, k0));
                    #pragma unroll
                    for (int h = 0; h < 2; h++) {
                        int ni = gq * 2 + h;
                        uint32_t bh[2] = {Bh[h], Bh[h + 2]};
                        uint32_t bl[2] = {Bl[h], Bl[h + 2]};
                        mma16816(gC[ni], AXh[ks], bh);
                        mma16816(gC[ni], AXh[ks], bl);
                    }
                }
            }
            #pragma unroll
            for (int e2 = 0; e2 < 2; e2++) {
                int jl = w * 16 + g + e2 * 8;
                float sj = sqjs[jl];
                #pragma unroll
                for (int ni = 0; ni < 8; ni++) {
                    int il = ni * 8 + tg * 2;
                    float d0 = sj + sqis[ch * 64 + il]     - 2.f * gC[ni][e2 * 2];
                    float d1 = sj + sqis[ch * 64 + il + 1] - 2.f * gC[ni][e2 * 2 + 1];
                    *(uint32_t*)(smc + 16384 + jl * 128 + ((il * 2) ^ ((jl & 7) << 4))) =
                        packh2(d0, d1);
                }
            }
        }
        // c-GEMM (3-term)
        float cC[8][4];
        #pragma unroll
        for (int b = 0; b < 8; b++)
            #pragma unroll
            for (int e = 0; e < 4; e++) cC[b][e] = 0.f;
        #pragma unroll
        for (int ks = 0; ks < 4; ks++) {
            int k0 = ks * 16;
            #pragma unroll
            for (int gq = 0; gq < 4; gq++) {
                uint32_t Bh[4], Bl[4];
                ldm_x4(Bh, frag_addr(xbh, lane, gq * 16, k0));
                ldm_x4(Bl, frag_addr(xbl, lane, gq * 16, k0));
                #pragma unroll
                for (int h = 0; h < 2; h++) {
                    int ni = gq * 2 + h;
                    uint32_t bh[2] = {Bh[h], Bh[h + 2]};
                    uint32_t bl[2] = {Bl[h], Bl[h + 2]};
                    mma16816(cC[ni], AUh[ks], bh);
                    mma16816(cC[ni], AUh[ks], bl);
                    mma16816(cC[ni], AUl[ks], bh);
                }
            }
        }
        // weights -> Wh
        #pragma unroll
        for (int e2 = 0; e2 < 2; e2++) {
            int jl = w * 16 + g + e2 * 8;
            float bj = bUs[jl], su2 = su2s[jl];
            #pragma unroll
            for (int ni = 0; ni < 8; ni++) {
                int il = ni * 8 + tg * 2;
                float2 dd = __half22float2(
                    *(__half2*)(smc + 16384 + jl * 128 + ((il * 2) ^ ((jl & 7) << 4))));
                float wv[2], d2v[2] = {dd.x, dd.y};
                #pragma unroll
                for (int q = 0; q < 2; q++) {
                    float cp = cC[ni][e2 * 2 + q] - bj;
                    float du = fmaxf(fabsf(cp) * su2, 1e-3f);
                    float dv = asqrt(fmaxf(d2v[q] - du * du, 1e-6f));
                    wv[q] = w2f(dv, a1) * w2f(du, a2);
                }
                rs2[e2] += wv[0] + wv[1];
                *(uint32_t*)(smc + SWZ(jl * 128 + il * 2)) = packh2(wv[0], wv[1]);
            }
        }
        __syncthreads();
        // acc-GEMM (1-term)
        #pragma unroll
        for (int ks = 0; ks < 4; ks++) {
            int k0 = ks * 16;
            uint32_t Awh[4];
            ldm_x4(Awh, frag_addr(sb, lane, w * 16, k0));
            #pragma unroll
            for (int gq = 0; gq < 4; gq++) {
                uint32_t Bh[4];
                ldm_x4t(Bh, frag_addr(xbh, lane, k0, gq * 16));
                #pragma unroll
                for (int h = 0; h < 2; h++) {
                    uint32_t bh[2] = {Bh[h * 2], Bh[h * 2 + 1]};
                    mma16816(accC[gq * 2 + h], Awh, bh);
                }
            }
        }
    }
    // epilogue
    #pragma unroll
    for (int e2 = 0; e2 < 2; e2++) {
        float s = rs2[e2];
        s += __shfl_xor_sync(0xffffffffu, s, 1);
        s += __shfl_xor_sync(0xffffffffu, s, 2);
        if (tg == 0) atomicAdd(&g_S2[j0 + w * 16 + g + e2 * 8], s);
    }
    #pragma unroll
    for (int ni = 0; ni < 8; ni++)
        #pragma unroll
        for (int e = 0; e < 4; e++) {
            int j = j0 + w * 16 + g + (e >> 1) * 8;
            int p = ni * 8 + tg * 2 + (e & 1);
            atomicAdd(&g_accZ[(size_t)j * P + p], accC[ni][e]);
        }
}

// ---------------- K: output ----------------
__global__ void k_out(const float* __restrict__ x, float* __restrict__ out, int n) {
    int idx = blockIdx.x * blockDim.x + threadIdx.x;
    if (idx >= n * P) return;
    int j = idx >> 6;
    float e = g_accZ[idx] / g_S2[j];
    if (isnan(e)) e = x[idx];
    out[idx] = e;
}

extern "C" void kernel_launch(void* const* d_in, const int* in_sizes, int n_in,
                              void* d_out, int out_size) {
    const float* x  = (const float*)d_in[0];
    const float* r0 = (const float*)d_in[1];
    const float* r1 = (const float*)d_in[2];
    const float* r2 = (const float*)d_in[3];
    float* out = (float*)d_out;
    const int n = in_sizes[0] / P;  // 4096
    const int nb = n / 128;

    k_prep<<<(n + 7) / 8, 256>>>(x, n);

    cudaFuncSetAttribute(k_grammax, cudaFuncAttributeMaxDynamicSharedMemorySize, 50176);
    k_grammax<<<nb * (nb + 1) / 2, 256, 50176>>>(n);

    cudaFuncSetAttribute(k_alpha, cudaFuncAttributeMaxDynamicSharedMemorySize, 50176);
    k_alpha<<<dim3(nb, 32), 256, 50176>>>(r0, n);

    k_U<<<(n + 7) / 8, 256>>>(x, n);

    cudaFuncSetAttribute(k_beta, cudaFuncAttributeMaxDynamicSharedMemorySize, 84480);
    k_beta<<<dim3(nb, 16), 256, 84480>>>(r1, r2, n);

    k_out<<<(n * P + 255) / 256, 256>>>(x, out, n);
}